// round 9
// baseline (speedup 1.0000x reference)
#include <cuda_runtime.h>
#include <cuda_fp16.h>
#include <stdint.h>

// ---------------- problem constants ----------------
#define B_N 4
#define C_N 96
#define H_N 256
#define W_N 256
#define CHS (H_N * W_N)
#define NTH 128
#define KSTEPS 18            // 288 / 16

// Y tile: 96 k-rows x 64 pixels (2 image rows x 32 cols), fp16
#define YSTR 72              // halves per row (64 + 8 pad) -> 144B = 9*16B
#define YROW_B (YSTR * 2)    // 144
#define YSZ (96 * YROW_B)    // 13824
#define OFF_Y0 0
#define OFF_Y1 YSZ           // 13824
#define OFF_Y2 (2 * YSZ)     // 27648
#define SMEM_SZ (3 * YSZ)    // 41472

// W fragments: [kstep][pair q=0..5][lane] uint4 =
//   {b0(nt=2q), b1(2q), b0(2q+1), b1(2q+1)}  -- read directly from gmem (L1-hot)
__device__ uint4 g_Wf[KSTEPS * 6 * 32];

// ---------------- helpers ----------------
static __device__ __forceinline__ uint32_t smem_u32(const void* p) {
    uint32_t a;
    asm("{ .reg .u64 t; cvta.to.shared.u64 t, %1; cvt.u32.u64 %0, t; }" : "=r"(a) : "l"(p));
    return a;
}
static __device__ __forceinline__ uint32_t pack_h2(float a, float b) {
    __half2 h = __floats2half2_rn(a, b);
    return *(uint32_t*)&h;
}
static __device__ __forceinline__ void ldsm4t(uint32_t* r, uint32_t addr) {
    asm volatile("ldmatrix.sync.aligned.m8n8.x4.trans.shared.b16 {%0,%1,%2,%3}, [%4];"
                 : "=r"(r[0]), "=r"(r[1]), "=r"(r[2]), "=r"(r[3]) : "r"(addr));
}
static __device__ __forceinline__ void mma16816(float* d, const uint32_t* a,
                                                uint32_t b0, uint32_t b1) {
    asm volatile(
        "mma.sync.aligned.m16n8k16.row.col.f32.f16.f16.f32 "
        "{%0,%1,%2,%3}, {%4,%5,%6,%7}, {%8,%9}, {%0,%1,%2,%3};"
        : "+f"(d[0]), "+f"(d[1]), "+f"(d[2]), "+f"(d[3])
        : "r"(a[0]), "r"(a[1]), "r"(a[2]), "r"(a[3]), "r"(b0), "r"(b1));
}
static __device__ __forceinline__ float ffm_sel(float a, float b) {
    return (fabsf(a) >= fabsf(b)) ? a : b;
}

// ---------------- prep: W -> per-lane fp16 B fragments ----------------
__global__ void prep_w_kernel(const float* __restrict__ w) {
    int i = blockIdx.x * 256 + threadIdx.x;
    if (i >= KSTEPS * 6 * 32) return;
    int lane = i & 31;
    int q = (i >> 5) % 6;
    int ks = i / (6 * 32);
    int t = lane & 3;
    int g = lane >> 2;
    int k0 = ks * 16;
    int oe = (2 * q) * 8 + g;
    int oo = (2 * q + 1) * 8 + g;
    uint4 v;
    v.x = pack_h2(w[oe * 288 + k0 + 2 * t],     w[oe * 288 + k0 + 2 * t + 1]);
    v.y = pack_h2(w[oe * 288 + k0 + 2 * t + 8], w[oe * 288 + k0 + 2 * t + 9]);
    v.z = pack_h2(w[oo * 288 + k0 + 2 * t],     w[oo * 288 + k0 + 2 * t + 1]);
    v.w = pack_h2(w[oo * 288 + k0 + 2 * t + 8], w[oo * 288 + k0 + 2 * t + 9]);
    g_Wf[i] = v;
}

// ---------------- fused DWT + concat + 1x1 conv: 64-pixel blocks, hi-only fp16 ----------------
__global__ void __launch_bounds__(NTH, 5)
fused_mma_kernel(const float* __restrict__ x1, const float* __restrict__ x2,
                 const float* __restrict__ x3, float* __restrict__ out) {
    extern __shared__ unsigned char smem[];
    const uint32_t sb = smem_u32(smem);

    const int tid = threadIdx.x;
    const int wid = tid >> 5;
    const int lane = tid & 31;
    const int bid = blockIdx.x;
    const int b  = bid >> 10;           // 1024 blocks per batch
    const int r  = (bid >> 3) & 127;    // row-pair index
    const int j0 = (bid & 7) << 5;      // col base: 0,32,...,224

    const int pg = wid & 1;             // image row within pair (32 pixels)
    const int oh = wid >> 1;            // output half (48 outs)

    const int g2i = lane >> 3, jj = lane & 7;
    const int krow = ((g2i & 2) << 2) + jj;
    const int pxo  = (g2i & 1) << 3;
    const uint32_t lmoff0 = (uint32_t)(krow * YSTR + pg * 32 + pxo) * 2;
    const uint32_t lmoff1 = lmoff0 + 32;   // mtile 1: +16 pixels

    const int rowbase = ((b * C_N) * H_N + 2 * r) * W_N + j0;

    // ---- single staging pass: 96 k x 16 col-pairs = 1536 units, 12/thread ----
    {
        #pragma unroll 4
        for (int it = 0; it < 12; ++it) {
            int q = tid + it * NTH;
            int k = q >> 4;
            int u = q & 15;
            int off = rowbase + k * CHS + 2 * u;
            float2 t1 = *(const float2*)(x1 + off);
            float2 g1 = *(const float2*)(x1 + off + W_N);
            float2 t2 = *(const float2*)(x2 + off);
            float2 g2v = *(const float2*)(x2 + off + W_N);
            float2 t3 = *(const float2*)(x3 + off);
            float2 g3 = *(const float2*)(x3 + off + W_N);

            // x2 / x3 hi images straight from registers
            uint32_t* y1 = (uint32_t*)(smem + OFF_Y1 + k * YROW_B);
            uint32_t* y2 = (uint32_t*)(smem + OFF_Y2 + k * YROW_B);
            y1[u]      = pack_h2(t2.x, t2.y);
            y1[16 + u] = pack_h2(g2v.x, g2v.y);
            y2[u]      = pack_h2(t3.x, t3.y);
            y2[16 + u] = pack_h2(g3.x, g3.y);

            // DWT -> ffm -> IDWT for x_rec (chunk0)
            float s1, s2, w1, w2;
            s1 = t1.x + g1.x; s2 = t1.y + g1.y; w1 = g1.x - t1.x; w2 = g1.y - t1.y;
            float A1 = 0.5f*(s1+s2), B1 = 0.5f*(s2-s1), C1 = 0.5f*(w1+w2), D1 = 0.5f*(w2-w1);
            s1 = t2.x + g2v.x; s2 = t2.y + g2v.y; w1 = g2v.x - t2.x; w2 = g2v.y - t2.y;
            float A2 = 0.5f*(s1+s2), B2 = 0.5f*(s2-s1), C2 = 0.5f*(w1+w2), D2 = 0.5f*(w2-w1);
            s1 = t3.x + g3.x; s2 = t3.y + g3.y; w1 = g3.x - t3.x; w2 = g3.y - t3.y;
            float A3 = 0.5f*(s1+s2), B3 = 0.5f*(s2-s1), C3 = 0.5f*(w1+w2), D3 = 0.5f*(w2-w1);
            float A  = (A1 + A2 + A3) * (1.0f / 3.0f);
            float Bv = ffm_sel(ffm_sel(B1, B2), B3);
            float Cv = ffm_sel(ffm_sel(C1, C2), C3);
            float Dv = ffm_sel(ffm_sel(D1, D2), D3);
            float v0 = 0.5f * (A - Bv - Cv + Dv);
            float v1 = 0.5f * (A + Bv - Cv - Dv);
            float v2 = 0.5f * (A - Bv + Cv - Dv);
            float v3 = 0.5f * (A + Bv + Cv + Dv);
            uint32_t* y0 = (uint32_t*)(smem + OFF_Y0 + k * YROW_B);
            y0[u]      = pack_h2(v0, v1);
            y0[16 + u] = pack_h2(v2, v3);
        }
    }
    __syncthreads();

    float d[2][6][4];
    #pragma unroll
    for (int mt = 0; mt < 2; ++mt)
        #pragma unroll
        for (int nt = 0; nt < 6; ++nt)
            #pragma unroll
            for (int q = 0; q < 4; ++q) d[mt][nt][q] = 0.0f;

    // ---- one long GEMM: 18 k-steps, hi-only; W pipelined from gmem (L1-hot) ----
    const uint4* wbase = g_Wf + oh * 3 * 32 + lane;
    uint4 wc0 = __ldg(wbase);
    uint4 wc1 = __ldg(wbase + 32);
    uint4 wc2 = __ldg(wbase + 64);

    #pragma unroll
    for (int ks = 0; ks < KSTEPS; ++ks) {
        const int chunk = ks / 6;
        const int ksl = ks % 6;
        const uint32_t ybase = (chunk == 0) ? OFF_Y0 : (chunk == 1) ? OFF_Y1 : OFF_Y2;
        const uint32_t kadd = (uint32_t)(ksl * 16 * YROW_B);

        uint4 wn0, wn1, wn2;
        if (ks + 1 < KSTEPS) {
            const uint4* wnx = wbase + (ks + 1) * 192;
            wn0 = __ldg(wnx);
            wn1 = __ldg(wnx + 32);
            wn2 = __ldg(wnx + 64);
        }

        uint32_t ah[2][4];
        ldsm4t(ah[0], sb + ybase + kadd + lmoff0);
        ldsm4t(ah[1], sb + ybase + kadd + lmoff1);

        #pragma unroll
        for (int mt = 0; mt < 2; ++mt) {
            mma16816(d[mt][0], ah[mt], wc0.x, wc0.y);
            mma16816(d[mt][1], ah[mt], wc0.z, wc0.w);
            mma16816(d[mt][2], ah[mt], wc1.x, wc1.y);
            mma16816(d[mt][3], ah[mt], wc1.z, wc1.w);
            mma16816(d[mt][4], ah[mt], wc2.x, wc2.y);
            mma16816(d[mt][5], ah[mt], wc2.z, wc2.w);
        }
        wc0 = wn0; wc1 = wn1; wc2 = wn2;
    }

    // ---- epilogue ----
    {
        const int g = lane >> 2, t = lane & 3;
        #pragma unroll
        for (int mt = 0; mt < 2; ++mt) {
            float* ob = out + ((size_t)(b * C_N + oh * 48) * H_N + 2 * r + pg) * W_N
                        + j0 + mt * 16 + g;
            #pragma unroll
            for (int nt = 0; nt < 6; ++nt) {
                float* oc = ob + (size_t)(nt * 8 + 2 * t) * CHS;
                oc[0]       = d[mt][nt][0];
                oc[CHS]     = d[mt][nt][1];
                oc[8]       = d[mt][nt][2];
                oc[CHS + 8] = d[mt][nt][3];
            }
        }
    }
}

// ---------------- launch ----------------
extern "C" void kernel_launch(void* const* d_in, const int* in_sizes, int n_in,
                              void* d_out, int out_size) {
    const float* xs[3];
    const float* w = nullptr;
    int nx = 0;
    for (int i = 0; i < n_in; ++i) {
        if (in_sizes[i] == C_N * 288) w = (const float*)d_in[i];
        else if (nx < 3) xs[nx++] = (const float*)d_in[i];
    }
    float* out = (float*)d_out;

    cudaFuncSetAttribute(fused_mma_kernel,
                         cudaFuncAttributeMaxDynamicSharedMemorySize, SMEM_SZ);

    prep_w_kernel<<<(KSTEPS * 6 * 32 + 255) / 256, 256>>>(w);
    fused_mma_kernel<<<B_N * 128 * 8, NTH, SMEM_SZ>>>(xs[0], xs[1], xs[2], out);
}

// round 10
// speedup vs baseline: 1.2830x; 1.2830x over previous
#include <cuda_runtime.h>
#include <cuda_fp16.h>
#include <stdint.h>

// ---------------- problem constants ----------------
#define B_N 4
#define C_N 96
#define H_N 256
#define W_N 256
#define CHS (H_N * W_N)
#define NTH 128
#define KSTEPS 18            // 288 / 16

// Y tile: 96 k-rows x 64 pixels (2 image rows x 32 cols), fp16
#define YSTR 72              // halves per row (64 + 8 pad) -> 144B = 9*16B
#define YROW_B (YSTR * 2)    // 144
#define YSZ (96 * YROW_B)    // 13824
#define OFF_Y0 0
#define OFF_Y1 YSZ           // 13824
#define OFF_Y2 (2 * YSZ)     // 27648
#define SMEM_SZ (3 * YSZ)    // 41472

// W fragments: [kstep][pair q=0..5][lane] uint4, +1 dummy kstep so the
// software prefetch never needs a branch (dummy values read, never used).
__device__ uint4 g_Wf[(KSTEPS + 1) * 6 * 32];

// ---------------- helpers ----------------
static __device__ __forceinline__ uint32_t smem_u32(const void* p) {
    uint32_t a;
    asm("{ .reg .u64 t; cvta.to.shared.u64 t, %1; cvt.u32.u64 %0, t; }" : "=r"(a) : "l"(p));
    return a;
}
static __device__ __forceinline__ uint32_t pack_h2(float a, float b) {
    __half2 h = __floats2half2_rn(a, b);
    return *(uint32_t*)&h;
}
static __device__ __forceinline__ void ldsm4t(uint32_t* r, uint32_t addr) {
    asm volatile("ldmatrix.sync.aligned.m8n8.x4.trans.shared.b16 {%0,%1,%2,%3}, [%4];"
                 : "=r"(r[0]), "=r"(r[1]), "=r"(r[2]), "=r"(r[3]) : "r"(addr));
}
static __device__ __forceinline__ void mma16816(float* d, const uint32_t* a,
                                                uint32_t b0, uint32_t b1) {
    asm volatile(
        "mma.sync.aligned.m16n8k16.row.col.f32.f16.f16.f32 "
        "{%0,%1,%2,%3}, {%4,%5,%6,%7}, {%8,%9}, {%0,%1,%2,%3};"
        : "+f"(d[0]), "+f"(d[1]), "+f"(d[2]), "+f"(d[3])
        : "r"(a[0]), "r"(a[1]), "r"(a[2]), "r"(a[3]), "r"(b0), "r"(b1));
}
static __device__ __forceinline__ float ffm_sel(float a, float b) {
    return (fabsf(a) >= fabsf(b)) ? a : b;
}

// ---------------- prep: W -> per-lane fp16 B fragments ----------------
__global__ void prep_w_kernel(const float* __restrict__ w) {
    int i = blockIdx.x * 256 + threadIdx.x;
    if (i >= (KSTEPS + 1) * 6 * 32) return;
    if (i >= KSTEPS * 6 * 32) {       // dummy pad kstep: deterministic zeros
        g_Wf[i] = make_uint4(0, 0, 0, 0);
        return;
    }
    int lane = i & 31;
    int q = (i >> 5) % 6;
    int ks = i / (6 * 32);
    int t = lane & 3;
    int g = lane >> 2;
    int k0 = ks * 16;
    int oe = (2 * q) * 8 + g;
    int oo = (2 * q + 1) * 8 + g;
    uint4 v;
    v.x = pack_h2(w[oe * 288 + k0 + 2 * t],     w[oe * 288 + k0 + 2 * t + 1]);
    v.y = pack_h2(w[oe * 288 + k0 + 2 * t + 8], w[oe * 288 + k0 + 2 * t + 9]);
    v.z = pack_h2(w[oo * 288 + k0 + 2 * t],     w[oo * 288 + k0 + 2 * t + 1]);
    v.w = pack_h2(w[oo * 288 + k0 + 2 * t + 8], w[oo * 288 + k0 + 2 * t + 9]);
    g_Wf[i] = v;
}

// ---------------- fused DWT + concat + 1x1 conv: 64-pixel blocks, hi-only fp16 ----------------
__global__ void __launch_bounds__(NTH, 4)
fused_mma_kernel(const float* __restrict__ x1, const float* __restrict__ x2,
                 const float* __restrict__ x3, float* __restrict__ out) {
    extern __shared__ unsigned char smem[];
    const uint32_t sb = smem_u32(smem);

    const int tid = threadIdx.x;
    const int wid = tid >> 5;
    const int lane = tid & 31;
    const int bid = blockIdx.x;
    const int b  = bid >> 10;           // 1024 blocks per batch
    const int r  = (bid >> 3) & 127;    // row-pair index
    const int j0 = (bid & 7) << 5;      // col base: 0,32,...,224

    const int pg = wid & 1;             // image row within pair (32 pixels)
    const int oh = wid >> 1;            // output half (48 outs)

    const int g2i = lane >> 3, jj = lane & 7;
    const int krow = ((g2i & 2) << 2) + jj;
    const int pxo  = (g2i & 1) << 3;
    const uint32_t lmoff0 = (uint32_t)(krow * YSTR + pg * 32 + pxo) * 2;
    const uint32_t lmoff1 = lmoff0 + 32;   // mtile 1: +16 pixels

    const int rowbase = ((b * C_N) * H_N + 2 * r) * W_N + j0;

    // ---- single staging pass: 96 k x 8 col-quads = 768 units, 6/thread ----
    // Each unit: float4 per source per row = two 2x2 DWT blocks.
    {
        #pragma unroll
        for (int it = 0; it < 6; ++it) {
            int q = tid + it * NTH;
            int k = q >> 3;
            int u4 = q & 7;                   // quad index: cols 4*u4 .. 4*u4+3
            int off = rowbase + k * CHS + 4 * u4;
            float4 t1 = *(const float4*)(x1 + off);
            float4 g1 = *(const float4*)(x1 + off + W_N);
            float4 t2 = *(const float4*)(x2 + off);
            float4 g2v = *(const float4*)(x2 + off + W_N);
            float4 t3 = *(const float4*)(x3 + off);
            float4 g3 = *(const float4*)(x3 + off + W_N);

            // x2 / x3 hi images straight from registers (uint2 = 2 col-pairs)
            uint32_t* y1 = (uint32_t*)(smem + OFF_Y1 + k * YROW_B);
            uint32_t* y2 = (uint32_t*)(smem + OFF_Y2 + k * YROW_B);
            *(uint2*)(y1 + 2 * u4)      = make_uint2(pack_h2(t2.x, t2.y), pack_h2(t2.z, t2.w));
            *(uint2*)(y1 + 16 + 2 * u4) = make_uint2(pack_h2(g2v.x, g2v.y), pack_h2(g2v.z, g2v.w));
            *(uint2*)(y2 + 2 * u4)      = make_uint2(pack_h2(t3.x, t3.y), pack_h2(t3.z, t3.w));
            *(uint2*)(y2 + 16 + 2 * u4) = make_uint2(pack_h2(g3.x, g3.y), pack_h2(g3.z, g3.w));

            // DWT -> ffm -> IDWT for x_rec: two 2x2 blocks
            float r0[4], r1[4];               // [pair] results: r0 = even row, r1 = odd row
            #pragma unroll
            for (int blk = 0; blk < 2; ++blk) {
                float t1x = blk ? t1.z : t1.x, t1y = blk ? t1.w : t1.y;
                float g1x = blk ? g1.z : g1.x, g1y = blk ? g1.w : g1.y;
                float t2x = blk ? t2.z : t2.x, t2y = blk ? t2.w : t2.y;
                float g2x = blk ? g2v.z : g2v.x, g2y = blk ? g2v.w : g2v.y;
                float t3x = blk ? t3.z : t3.x, t3y = blk ? t3.w : t3.y;
                float g3x = blk ? g3.z : g3.x, g3y = blk ? g3.w : g3.y;
                float s1, s2, w1, w2;
                s1 = t1x + g1x; s2 = t1y + g1y; w1 = g1x - t1x; w2 = g1y - t1y;
                float A1 = 0.5f*(s1+s2), B1 = 0.5f*(s2-s1), C1 = 0.5f*(w1+w2), D1 = 0.5f*(w2-w1);
                s1 = t2x + g2x; s2 = t2y + g2y; w1 = g2x - t2x; w2 = g2y - t2y;
                float A2 = 0.5f*(s1+s2), B2 = 0.5f*(s2-s1), C2 = 0.5f*(w1+w2), D2 = 0.5f*(w2-w1);
                s1 = t3x + g3x; s2 = t3y + g3y; w1 = g3x - t3x; w2 = g3y - t3y;
                float A3 = 0.5f*(s1+s2), B3 = 0.5f*(s2-s1), C3 = 0.5f*(w1+w2), D3 = 0.5f*(w2-w1);
                float A  = (A1 + A2 + A3) * (1.0f / 3.0f);
                float Bv = ffm_sel(ffm_sel(B1, B2), B3);
                float Cv = ffm_sel(ffm_sel(C1, C2), C3);
                float Dv = ffm_sel(ffm_sel(D1, D2), D3);
                r0[2*blk]   = 0.5f * (A - Bv - Cv + Dv);
                r0[2*blk+1] = 0.5f * (A + Bv - Cv - Dv);
                r1[2*blk]   = 0.5f * (A - Bv + Cv - Dv);
                r1[2*blk+1] = 0.5f * (A + Bv + Cv + Dv);
            }
            uint32_t* y0 = (uint32_t*)(smem + OFF_Y0 + k * YROW_B);
            *(uint2*)(y0 + 2 * u4)      = make_uint2(pack_h2(r0[0], r0[1]), pack_h2(r0[2], r0[3]));
            *(uint2*)(y0 + 16 + 2 * u4) = make_uint2(pack_h2(r1[0], r1[1]), pack_h2(r1[2], r1[3]));
        }
    }
    __syncthreads();

    float d[2][6][4];
    #pragma unroll
    for (int mt = 0; mt < 2; ++mt)
        #pragma unroll
        for (int nt = 0; nt < 6; ++nt)
            #pragma unroll
            for (int q = 0; q < 4; ++q) d[mt][nt][q] = 0.0f;

    // ---- one long GEMM: 18 k-steps, hi-only; W pipelined from gmem (L1-hot) ----
    const uint4* wbase = g_Wf + oh * 3 * 32 + lane;
    uint4 wc0 = __ldg(wbase);
    uint4 wc1 = __ldg(wbase + 32);
    uint4 wc2 = __ldg(wbase + 64);

    #pragma unroll
    for (int ks = 0; ks < KSTEPS; ++ks) {
        const int chunk = ks / 6;
        const int ksl = ks % 6;
        const uint32_t ybase = (chunk == 0) ? OFF_Y0 : (chunk == 1) ? OFF_Y1 : OFF_Y2;
        const uint32_t kadd = (uint32_t)(ksl * 16 * YROW_B);

        // branch-free prefetch (pad kstep makes ks+1 always in-bounds)
        const uint4* wnx = wbase + (ks + 1) * 192;
        uint4 wn0 = __ldg(wnx);
        uint4 wn1 = __ldg(wnx + 32);
        uint4 wn2 = __ldg(wnx + 64);

        uint32_t ah[2][4];
        ldsm4t(ah[0], sb + ybase + kadd + lmoff0);
        ldsm4t(ah[1], sb + ybase + kadd + lmoff1);

        #pragma unroll
        for (int mt = 0; mt < 2; ++mt) {
            mma16816(d[mt][0], ah[mt], wc0.x, wc0.y);
            mma16816(d[mt][1], ah[mt], wc0.z, wc0.w);
            mma16816(d[mt][2], ah[mt], wc1.x, wc1.y);
            mma16816(d[mt][3], ah[mt], wc1.z, wc1.w);
            mma16816(d[mt][4], ah[mt], wc2.x, wc2.y);
            mma16816(d[mt][5], ah[mt], wc2.z, wc2.w);
        }
        wc0 = wn0; wc1 = wn1; wc2 = wn2;
    }

    // ---- epilogue ----
    {
        const int g = lane >> 2, t = lane & 3;
        #pragma unroll
        for (int mt = 0; mt < 2; ++mt) {
            float* ob = out + ((size_t)(b * C_N + oh * 48) * H_N + 2 * r + pg) * W_N
                        + j0 + mt * 16 + g;
            #pragma unroll
            for (int nt = 0; nt < 6; ++nt) {
                float* oc = ob + (size_t)(nt * 8 + 2 * t) * CHS;
                oc[0]       = d[mt][nt][0];
                oc[CHS]     = d[mt][nt][1];
                oc[8]       = d[mt][nt][2];
                oc[CHS + 8] = d[mt][nt][3];
            }
        }
    }
}

// ---------------- launch ----------------
extern "C" void kernel_launch(void* const* d_in, const int* in_sizes, int n_in,
                              void* d_out, int out_size) {
    const float* xs[3];
    const float* w = nullptr;
    int nx = 0;
    for (int i = 0; i < n_in; ++i) {
        if (in_sizes[i] == C_N * 288) w = (const float*)d_in[i];
        else if (nx < 3) xs[nx++] = (const float*)d_in[i];
    }
    float* out = (float*)d_out;

    cudaFuncSetAttribute(fused_mma_kernel,
                         cudaFuncAttributeMaxDynamicSharedMemorySize, SMEM_SZ);

    prep_w_kernel<<<((KSTEPS + 1) * 6 * 32 + 255) / 256, 256>>>(w);
    fused_mma_kernel<<<B_N * 128 * 8, NTH, SMEM_SZ>>>(xs[0], xs[1], xs[2], out);
}